// round 3
// baseline (speedup 1.0000x reference)
#include <cuda_runtime.h>
#include <math.h>

#define NMAX 20000
#define CDIM 64
#define NLMD 9
#define NBES 8
#define ZDIM 10

typedef unsigned long long ull;

// ---------------- f32x2 helpers (Blackwell packed fp32) ----------------
__device__ __forceinline__ ull dup2(float v) {
  ull r; asm("mov.b64 %0, {%1, %1};" : "=l"(r) : "f"(v)); return r;
}
__device__ __forceinline__ ull pack2(float a, float b) {
  ull r; asm("mov.b64 %0, {%1, %2};" : "=l"(r) : "f"(a), "f"(b)); return r;
}
__device__ __forceinline__ void unpack2(ull v, float& a, float& b) {
  asm("mov.b64 {%0, %1}, %2;" : "=f"(a), "=f"(b) : "l"(v));
}
__device__ __forceinline__ ull fma2(ull a, ull b, ull c) {
  ull d; asm("fma.rn.f32x2 %0, %1, %2, %3;" : "=l"(d) : "l"(a), "l"(b), "l"(c)); return d;
}
__device__ __forceinline__ void red2(float* p, float a, float b) {
  asm volatile("red.global.add.v2.f32 [%0], {%1, %2};" :: "l"(p), "f"(a), "f"(b) : "memory");
}

// ---------------- scratch (device globals; no allocation) ----------------
__device__ float g_msg[NMAX * NLMD * CDIM];   // [N][lm][c]
__device__ float g_htable[ZDIM * CDIM];
__device__ float g_xout[NMAX * CDIM];

// ---------------- zero the message buffer ----------------
__global__ void zero_msg_kernel(int n4) {
  int i = blockIdx.x * blockDim.x + threadIdx.x;
  float4* p = reinterpret_cast<float4*>(g_msg);
  if (i < n4) p[i] = make_float4(0.f, 0.f, 0.f, 0.f);
}

// ---------------- species embedding table ----------------
__global__ void htable_kernel(const float* __restrict__ W_embed,
                              const float* __restrict__ W_up) {
  int t = threadIdx.x;
  if (t < ZDIM * CDIM) {
    int z = t >> 6, c = t & 63;
    float acc = 0.f;
    #pragma unroll 8
    for (int k = 0; k < CDIM; k++)
      acc = fmaf(W_embed[z * CDIM + k], W_up[k * CDIM + c], acc);
    g_htable[t] = acc * (1.0f / (3.16227766016838f * 8.0f));  // /(sqrt(10)*sqrt(64))
  }
}

// ---------------- fused edge kernel ----------------
// One block == 128 edges. Activations kept TRANSPOSED as row-pairs:
//   At[k * 65 + pair]  (ull: rows 2*pair, 2*pair+1 of column k)
struct ESmem {
  ull   EFt[NBES * 65];    // transposed edge feats [k][pair]
  ull   Ta[64 * 65];       // transposed activation ping
  ull   Tb[64 * 65];       // transposed activation pong
  float w1[NBES * CDIM];
  float w2[CDIM * CDIM];
  float w3[CDIM * CDIM];
  float w4[CDIM * 192];
  float htab[ZDIM * CDIM];
  float Yb[128 * 9];
  int   recv[128];
  int   zs[128];
};

// C_T[64 x 128] = act(A_T[K x 128pairs] @ B[K x *] cols [Bc0, Bc0+64))
// thread map: rp = tid>>4 -> row-pairs {rp, rp+16, rp+32, rp+48}
//             cg = tid&15 -> cols {cg, cg+16, cg+32, cg+48}
template <int K, bool ACT>
__device__ __forceinline__ void gemm_t(const ull* __restrict__ At,
                                       const float* __restrict__ B, int Bs, int Bc0,
                                       ull* __restrict__ Ct, int tid) {
  int rp = tid >> 4, cg = tid & 15;
  ull acc[4][4];
  #pragma unroll
  for (int i = 0; i < 4; i++)
    #pragma unroll
    for (int j = 0; j < 4; j++) acc[i][j] = 0ull;

  #pragma unroll 4
  for (int k = 0; k < K; k++) {
    const float* Brow = B + k * Bs + Bc0 + cg;
    ull b0 = dup2(Brow[0]);
    ull b1 = dup2(Brow[16]);
    ull b2 = dup2(Brow[32]);
    ull b3 = dup2(Brow[48]);
    const ull* Arow = At + k * 65 + rp;
    ull a0 = Arow[0];
    ull a1 = Arow[16];
    ull a2 = Arow[32];
    ull a3 = Arow[48];
    acc[0][0] = fma2(a0, b0, acc[0][0]); acc[0][1] = fma2(a0, b1, acc[0][1]);
    acc[0][2] = fma2(a0, b2, acc[0][2]); acc[0][3] = fma2(a0, b3, acc[0][3]);
    acc[1][0] = fma2(a1, b0, acc[1][0]); acc[1][1] = fma2(a1, b1, acc[1][1]);
    acc[1][2] = fma2(a1, b2, acc[1][2]); acc[1][3] = fma2(a1, b3, acc[1][3]);
    acc[2][0] = fma2(a2, b0, acc[2][0]); acc[2][1] = fma2(a2, b1, acc[2][1]);
    acc[2][2] = fma2(a2, b2, acc[2][2]); acc[2][3] = fma2(a2, b3, acc[2][3]);
    acc[3][0] = fma2(a3, b0, acc[3][0]); acc[3][1] = fma2(a3, b1, acc[3][1]);
    acc[3][2] = fma2(a3, b2, acc[3][2]); acc[3][3] = fma2(a3, b3, acc[3][3]);
  }

  #pragma unroll
  for (int i = 0; i < 4; i++) {
    #pragma unroll
    for (int j = 0; j < 4; j++) {
      float lo, hi;
      unpack2(acc[i][j], lo, hi);
      if (ACT) {
        lo = lo / (1.0f + __expf(-lo));
        hi = hi / (1.0f + __expf(-hi));
      }
      Ct[(cg + 16 * j) * 65 + (rp + 16 * i)] = pack2(lo, hi);
    }
  }
}

extern __shared__ float esmem_raw[];

__global__ void __launch_bounds__(256, 1)
edge_kernel(const float* __restrict__ pos, const int* __restrict__ ai,
            const int* __restrict__ ei,
            const float* __restrict__ w1, const float* __restrict__ w2,
            const float* __restrict__ w3, const float* __restrict__ w4, int E) {
  ESmem& s = *reinterpret_cast<ESmem*>(esmem_raw);
  int tid = threadIdx.x;

  // stage weights + species table
  {
    float4* d; const float4* g;
    d = (float4*)s.w1;   g = (const float4*)w1;        for (int i = tid; i < NBES * CDIM / 4; i += 256) d[i] = g[i];
    d = (float4*)s.w2;   g = (const float4*)w2;        for (int i = tid; i < CDIM * CDIM / 4; i += 256) d[i] = g[i];
    d = (float4*)s.w3;   g = (const float4*)w3;        for (int i = tid; i < CDIM * CDIM / 4; i += 256) d[i] = g[i];
    d = (float4*)s.w4;   g = (const float4*)w4;        for (int i = tid; i < CDIM * 192 / 4; i += 256) d[i] = g[i];
    d = (float4*)s.htab; g = (const float4*)g_htable;  for (int i = tid; i < ZDIM * CDIM / 4; i += 256) d[i] = g[i];
  }

  // geometry: radial basis + cutoff + spherical harmonics
  if (tid < 128) {
    int eg = blockIdx.x * 128 + tid;
    float* Y   = s.Yb + tid * 9;
    float* EFf = (float*)s.EFt;  // float view, stride 130 per k
    if (eg < E) {
      int sd = ei[eg];
      int rv = ei[E + eg];
      float px = pos[3 * rv + 0] - pos[3 * sd + 0];
      float py = pos[3 * rv + 1] - pos[3 * sd + 1];
      float pz = pos[3 * rv + 2] - pos[3 * sd + 2];
      float r2 = px * px + py * py + pz * pz + 1e-12f;
      float r = sqrtf(r2);
      float inv = 1.0f / r;
      float ux = px * inv, uy = py * inv, uz = pz * inv;
      const float c3 = 1.73205080756888f;
      const float c5 = 2.23606797749979f;
      const float c15 = 3.87298334620742f;
      Y[0] = 1.0f;
      Y[1] = c3 * ux; Y[2] = c3 * uy; Y[3] = c3 * uz;
      Y[4] = c15 * ux * uy; Y[5] = c15 * uy * uz;
      Y[6] = 0.5f * c5 * (3.0f * uz * uz - 1.0f);
      Y[7] = c15 * ux * uz;
      Y[8] = 0.5f * c15 * (ux * ux - uy * uy);
      float u = fminf(r * 0.2f, 1.0f);
      float u2 = u * u, u4 = u2 * u2, u6 = u4 * u2, u7 = u6 * u, u8 = u4 * u4;
      float fc = 1.0f - 28.0f * u6 + 48.0f * u7 - 21.0f * u8;
      float pref = 0.632455532033676f * inv * fc;
      float w = 0.628318530717958648f * r;
      #pragma unroll
      for (int nb = 1; nb <= 8; nb++) EFf[(nb - 1) * 130 + tid] = pref * sinf(w * (float)nb);
      s.recv[tid] = rv;
      s.zs[tid] = ai[sd];
    } else {
      #pragma unroll
      for (int q = 0; q < 9; q++) Y[q] = 0.f;
      #pragma unroll
      for (int q = 0; q < 8; q++) EFf[q * 130 + tid] = 0.f;
      s.recv[tid] = -1;
      s.zs[tid] = 0;
    }
  }
  __syncthreads();

  gemm_t<8,  true >(s.EFt, s.w1, 64, 0, s.Ta, tid); __syncthreads();
  gemm_t<64, true >(s.Ta,  s.w2, 64, 0, s.Tb, tid); __syncthreads();
  gemm_t<64, true >(s.Tb,  s.w3, 64, 0, s.Ta, tid); __syncthreads();

  // layer 4 in 3 column-chunks (the 3 l-channels), each followed by scatter
  int wid = tid >> 5, lane = tid & 31;
  const float* Tbf = (const float*)s.Tb;
  #pragma unroll
  for (int l = 0; l < 3; l++) {
    gemm_t<64, false>(s.Ta, s.w4, 192, l * 64, s.Tb, tid);
    __syncthreads();
    int lm0 = (l == 0) ? 0 : ((l == 1) ? 1 : 4);
    int cnt = (l == 0) ? 1 : ((l == 1) ? 3 : 5);
    int c0 = 2 * lane;
    for (int e = wid; e < 128; e += 8) {
      int rv = s.recv[e];
      if (rv >= 0) {
        int zz = s.zs[e];
        float2 h2 = *reinterpret_cast<const float2*>(s.htab + zz * 64 + c0);
        float v0 = Tbf[c0 * 130 + e] * h2.x;
        float v1 = Tbf[(c0 + 1) * 130 + e] * h2.y;
        float* mp = g_msg + rv * 576 + c0;
        const float* Ye = s.Yb + e * 9 + lm0;
        for (int q = 0; q < cnt; q++) {
          float yv = Ye[q];
          red2(mp + (lm0 + q) * 64, v0 * yv, v1 * yv);
        }
      }
    }
    __syncthreads();
  }
}

// ---------------- per-(node, 2-channel) tensor contraction ----------------
__global__ void __launch_bounds__(256)
contract_kernel(const int* __restrict__ ai,
                const float* __restrict__ U3, const float* __restrict__ U2,
                const float* __restrict__ U1,
                const float* __restrict__ Wc3, const float* __restrict__ Wc2,
                const float* __restrict__ Wc1, int N) {
  __shared__ float4 sU3[729];  // [i][j][k] x p
  __shared__ float4 sU2[81];
  __shared__ float4 sU1[9];
  __shared__ float sW3[ZDIM * 4 * CDIM];
  __shared__ float sW2[ZDIM * 4 * CDIM];
  __shared__ float sW1[ZDIM * 4 * CDIM];
  int tid = threadIdx.x;
  for (int i = tid; i < 729; i += 256) sU3[i] = ((const float4*)U3)[i];
  for (int i = tid; i < 81;  i += 256) sU2[i] = ((const float4*)U2)[i];
  if (tid < 9) sU1[tid] = ((const float4*)U1)[tid];
  for (int i = tid; i < ZDIM * 64; i += 256) {
    ((float4*)sW3)[i] = ((const float4*)Wc3)[i];
    ((float4*)sW2)[i] = ((const float4*)Wc2)[i];
    ((float4*)sW1)[i] = ((const float4*)Wc1)[i];
  }
  __syncthreads();

  int idx = blockIdx.x * 256 + tid;
  if (idx >= N * 32) return;
  int n = idx >> 5, q = idx & 31, c0 = q * 2;
  int z = ai[n];

  float2 x[9];
  const float* mrow = g_msg + n * 576 + c0;
  #pragma unroll
  for (int i = 0; i < 9; i++) {
    float2 v = *reinterpret_cast<const float2*>(mrow + i * 64);
    x[i].x = v.x * (1.0f / 16.0f);
    x[i].y = v.y * (1.0f / 16.0f);
  }

  float2 w3p[4], w2p[4], w1p[4];
  #pragma unroll
  for (int p = 0; p < 4; p++) {
    w3p[p] = *reinterpret_cast<const float2*>(sW3 + z * 256 + p * 64 + c0);
    w2p[p] = *reinterpret_cast<const float2*>(sW2 + z * 256 + p * 64 + c0);
    w1p[p] = *reinterpret_cast<const float2*>(sW1 + z * 256 + p * 64 + c0);
  }

  float res0 = 0.f, res1 = 0.f;
  for (int j = 0; j < 9; j++) {
    float vj0 = 0.f, vj1 = 0.f;
    for (int k = 0; k < 9; k++) {
      // s_p = sum_i U3[i,j,k,p] * x_i   (per channel)
      float s0x = 0.f, s1x = 0.f, s2x = 0.f, s3x = 0.f;
      float s0y = 0.f, s1y = 0.f, s2y = 0.f, s3y = 0.f;
      #pragma unroll
      for (int i = 0; i < 9; i++) {
        float4 u3 = sU3[i * 81 + j * 9 + k];
        s0x = fmaf(u3.x, x[i].x, s0x); s0y = fmaf(u3.x, x[i].y, s0y);
        s1x = fmaf(u3.y, x[i].x, s1x); s1y = fmaf(u3.y, x[i].y, s1y);
        s2x = fmaf(u3.z, x[i].x, s2x); s2y = fmaf(u3.z, x[i].y, s2y);
        s3x = fmaf(u3.w, x[i].x, s3x); s3y = fmaf(u3.w, x[i].y, s3y);
      }
      float4 u2 = sU2[j * 9 + k];
      float t0 = u2.x * w2p[0].x + u2.y * w2p[1].x + u2.z * w2p[2].x + u2.w * w2p[3].x;
      float t1 = u2.x * w2p[0].y + u2.y * w2p[1].y + u2.z * w2p[2].y + u2.w * w2p[3].y;
      t0 = fmaf(s0x, w3p[0].x, t0); t1 = fmaf(s0y, w3p[0].y, t1);
      t0 = fmaf(s1x, w3p[1].x, t0); t1 = fmaf(s1y, w3p[1].y, t1);
      t0 = fmaf(s2x, w3p[2].x, t0); t1 = fmaf(s2y, w3p[2].y, t1);
      t0 = fmaf(s3x, w3p[3].x, t0); t1 = fmaf(s3y, w3p[3].y, t1);
      vj0 = fmaf(t0, x[k].x, vj0);
      vj1 = fmaf(t1, x[k].y, vj1);
    }
    float4 u1 = sU1[j];
    vj0 += u1.x * w1p[0].x + u1.y * w1p[1].x + u1.z * w1p[2].x + u1.w * w1p[3].x;
    vj1 += u1.x * w1p[0].y + u1.y * w1p[1].y + u1.z * w1p[2].y + u1.w * w1p[3].y;
    res0 = fmaf(vj0, x[j].x, res0);
    res1 = fmaf(vj1, x[j].y, res1);
  }
  *reinterpret_cast<float2*>(g_xout + n * 64 + c0) = make_float2(res0, res1);
}

// ---------------- final output GEMM: out = xout @ W_out / 8 ----------------
__global__ void __launch_bounds__(256)
out_kernel(const float* __restrict__ W_out, float* __restrict__ out, int N) {
  __shared__ float sW[64 * 64];
  __shared__ float sX[64 * 68];
  int tid = threadIdx.x;
  int n0 = blockIdx.x * 64;
  for (int i = tid; i < 1024; i += 256) ((float4*)sW)[i] = ((const float4*)W_out)[i];
  for (int i = tid; i < 64 * 16; i += 256) {
    int r = i >> 4, c4 = i & 15;
    float4 v = make_float4(0.f, 0.f, 0.f, 0.f);
    if (n0 + r < N) v = *reinterpret_cast<const float4*>(g_xout + (n0 + r) * 64 + c4 * 4);
    *reinterpret_cast<float4*>(sX + r * 68 + c4 * 4) = v;
  }
  __syncthreads();
  int rg = tid >> 4, cg = tid & 15;
  float acc[4][4];
  #pragma unroll
  for (int i = 0; i < 4; i++) { acc[i][0] = 0.f; acc[i][1] = 0.f; acc[i][2] = 0.f; acc[i][3] = 0.f; }
  #pragma unroll 4
  for (int k = 0; k < 64; k++) {
    float4 b = *reinterpret_cast<const float4*>(sW + k * 64 + cg * 4);
    #pragma unroll
    for (int i = 0; i < 4; i++) {
      float a = sX[(rg + 16 * i) * 68 + k];
      acc[i][0] = fmaf(a, b.x, acc[i][0]);
      acc[i][1] = fmaf(a, b.y, acc[i][1]);
      acc[i][2] = fmaf(a, b.z, acc[i][2]);
      acc[i][3] = fmaf(a, b.w, acc[i][3]);
    }
  }
  #pragma unroll
  for (int i = 0; i < 4; i++) {
    int n = n0 + rg + 16 * i;
    if (n < N) {
      *reinterpret_cast<float4*>(out + n * 64 + cg * 4) =
          make_float4(acc[i][0] * 0.125f, acc[i][1] * 0.125f,
                      acc[i][2] * 0.125f, acc[i][3] * 0.125f);
    }
  }
}

// ---------------- launch ----------------
extern "C" void kernel_launch(void* const* d_in, const int* in_sizes, int n_in,
                              void* d_out, int out_size) {
  const float* positions = (const float*)d_in[0];
  const int*   ai        = (const int*)d_in[1];
  const int*   ei        = (const int*)d_in[2];
  const float* W_embed   = (const float*)d_in[3];
  const float* W_up      = (const float*)d_in[4];
  const float* w1        = (const float*)d_in[5];
  const float* w2        = (const float*)d_in[6];
  const float* w3        = (const float*)d_in[7];
  const float* w4        = (const float*)d_in[8];
  const float* U3        = (const float*)d_in[9];
  const float* U2        = (const float*)d_in[10];
  const float* U1        = (const float*)d_in[11];
  const float* Wc3       = (const float*)d_in[12];
  const float* Wc2       = (const float*)d_in[13];
  const float* Wc1       = (const float*)d_in[14];
  const float* W_out     = (const float*)d_in[15];
  float* out = (float*)d_out;

  int N = in_sizes[0] / 3;
  int E = in_sizes[2] / 2;

  cudaFuncSetAttribute(edge_kernel, cudaFuncAttributeMaxDynamicSharedMemorySize,
                       (int)sizeof(ESmem));

  int msg4 = (N * 576) / 4;
  zero_msg_kernel<<<(msg4 + 255) / 256, 256>>>(msg4);
  htable_kernel<<<1, 640>>>(W_embed, W_up);
  int ntiles = (E + 127) / 128;
  edge_kernel<<<ntiles, 256, sizeof(ESmem)>>>(positions, ai, ei, w1, w2, w3, w4, E);
  int nc = N * 32;
  contract_kernel<<<(nc + 255) / 256, 256>>>(ai, U3, U2, U1, Wc3, Wc2, Wc1, N);
  out_kernel<<<(N + 63) / 64, 256>>>(W_out, out, N);

  (void)n_in; (void)out_size;
}

// round 4
// speedup vs baseline: 1.3793x; 1.3793x over previous
#include <cuda_runtime.h>
#include <math.h>

#define NMAX 20000
#define CDIM 64
#define NLMD 9
#define NBES 8
#define ZDIM 10

// ---------------- helpers ----------------
__device__ __forceinline__ void red2(float* p, float a, float b) {
  asm volatile("red.global.add.v2.f32 [%0], {%1, %2};" :: "l"(p), "f"(a), "f"(b) : "memory");
}

// ---------------- scratch (device globals; no allocation) ----------------
__device__ float g_msg[NMAX * NLMD * CDIM];   // [N][lm][c]  46.08 MB
__device__ float g_htable[ZDIM * CDIM];
__device__ float g_xout[NMAX * CDIM];

// ---------------- zero the message buffer ----------------
__global__ void zero_msg_kernel(int n4) {
  int i = blockIdx.x * blockDim.x + threadIdx.x;
  float4* p = reinterpret_cast<float4*>(g_msg);
  if (i < n4) p[i] = make_float4(0.f, 0.f, 0.f, 0.f);
}

// ---------------- species embedding table ----------------
__global__ void htable_kernel(const float* __restrict__ W_embed,
                              const float* __restrict__ W_up) {
  int t = threadIdx.x;
  if (t < ZDIM * CDIM) {
    int z = t >> 6, c = t & 63;
    float acc = 0.f;
    #pragma unroll 8
    for (int k = 0; k < CDIM; k++)
      acc = fmaf(W_embed[z * CDIM + k], W_up[k * CDIM + c], acc);
    g_htable[t] = acc * (1.0f / (3.16227766016838f * 8.0f));  // /(sqrt(10)*sqrt(64))
  }
}

// ---------------- fused edge kernel ----------------
// One block == 128 edges. All MLP weights + activations in shared memory.
struct ESmem {
  float w1[NBES * CDIM];   // 512
  float w2[CDIM * CDIM];   // 4096
  float w3[CDIM * CDIM];   // 4096
  float w4[CDIM * 192];    // 12288
  float htab[ZDIM * CDIM]; // 640
  float EF[128 * 9];       // edge feats (8 used, stride 9)
  float Fa[128 * 68];      // activation ping
  float Fb[128 * 68];      // activation pong
  float Yb[128 * 9];       // spherical harmonics
  int   recv[128];
  int   zs[128];
};

// C[128x64] = act(A[128xK] @ B[K x *] cols [Bc0, Bc0+64)), C stride 68.
template <int K, bool ACT>
__device__ __forceinline__ void gemm128(const float* __restrict__ A, int As,
                                        const float* __restrict__ B, int Bs, int Bc0,
                                        float* __restrict__ Cm, int tid) {
  int rg = tid >> 4, cg = tid & 15;
  float acc[8][4];
  #pragma unroll
  for (int i = 0; i < 8; i++) { acc[i][0] = 0.f; acc[i][1] = 0.f; acc[i][2] = 0.f; acc[i][3] = 0.f; }
  #pragma unroll 4
  for (int k = 0; k < K; k++) {
    float4 b = *reinterpret_cast<const float4*>(B + k * Bs + Bc0 + cg * 4);
    #pragma unroll
    for (int i = 0; i < 8; i++) {
      float a = A[(rg + 16 * i) * As + k];
      acc[i][0] = fmaf(a, b.x, acc[i][0]);
      acc[i][1] = fmaf(a, b.y, acc[i][1]);
      acc[i][2] = fmaf(a, b.z, acc[i][2]);
      acc[i][3] = fmaf(a, b.w, acc[i][3]);
    }
  }
  #pragma unroll
  for (int i = 0; i < 8; i++) {
    float vv0 = acc[i][0], vv1 = acc[i][1], vv2 = acc[i][2], vv3 = acc[i][3];
    if (ACT) {
      vv0 = vv0 / (1.0f + __expf(-vv0));
      vv1 = vv1 / (1.0f + __expf(-vv1));
      vv2 = vv2 / (1.0f + __expf(-vv2));
      vv3 = vv3 / (1.0f + __expf(-vv3));
    }
    *reinterpret_cast<float4*>(Cm + (rg + 16 * i) * 68 + cg * 4) =
        make_float4(vv0, vv1, vv2, vv3);
  }
}

// GEMM producing accumulators only (for the layer-4 + scatter fusion).
template <int K>
__device__ __forceinline__ void gemm128_reg(const float* __restrict__ A, int As,
                                            const float* __restrict__ B, int Bs, int Bc0,
                                            float acc[8][4], int tid) {
  int rg = tid >> 4, cg = tid & 15;
  #pragma unroll
  for (int i = 0; i < 8; i++) { acc[i][0] = 0.f; acc[i][1] = 0.f; acc[i][2] = 0.f; acc[i][3] = 0.f; }
  #pragma unroll 4
  for (int k = 0; k < K; k++) {
    float4 b = *reinterpret_cast<const float4*>(B + k * Bs + Bc0 + cg * 4);
    #pragma unroll
    for (int i = 0; i < 8; i++) {
      float a = A[(rg + 16 * i) * As + k];
      acc[i][0] = fmaf(a, b.x, acc[i][0]);
      acc[i][1] = fmaf(a, b.y, acc[i][1]);
      acc[i][2] = fmaf(a, b.z, acc[i][2]);
      acc[i][3] = fmaf(a, b.w, acc[i][3]);
    }
  }
}

extern __shared__ float esmem_raw[];

__global__ void __launch_bounds__(256, 1)
edge_kernel(const float* __restrict__ pos, const int* __restrict__ ai,
            const int* __restrict__ ei,
            const float* __restrict__ w1, const float* __restrict__ w2,
            const float* __restrict__ w3, const float* __restrict__ w4, int E) {
  ESmem& s = *reinterpret_cast<ESmem*>(esmem_raw);
  int tid = threadIdx.x;

  // stage weights + species table
  {
    float4* d; const float4* g;
    d = (float4*)s.w1;   g = (const float4*)w1;        for (int i = tid; i < NBES * CDIM / 4; i += 256) d[i] = g[i];
    d = (float4*)s.w2;   g = (const float4*)w2;        for (int i = tid; i < CDIM * CDIM / 4; i += 256) d[i] = g[i];
    d = (float4*)s.w3;   g = (const float4*)w3;        for (int i = tid; i < CDIM * CDIM / 4; i += 256) d[i] = g[i];
    d = (float4*)s.w4;   g = (const float4*)w4;        for (int i = tid; i < CDIM * 192 / 4; i += 256) d[i] = g[i];
    d = (float4*)s.htab; g = (const float4*)g_htable;  for (int i = tid; i < ZDIM * CDIM / 4; i += 256) d[i] = g[i];
  }

  // geometry: radial basis + cutoff + spherical harmonics
  if (tid < 128) {
    int eg = blockIdx.x * 128 + tid;
    float* Y  = s.Yb + tid * 9;
    float* ef = s.EF + tid * 9;
    if (eg < E) {
      int sd = ei[eg];
      int rv = ei[E + eg];
      float px = pos[3 * rv + 0] - pos[3 * sd + 0];
      float py = pos[3 * rv + 1] - pos[3 * sd + 1];
      float pz = pos[3 * rv + 2] - pos[3 * sd + 2];
      float r2 = px * px + py * py + pz * pz + 1e-12f;
      float r = sqrtf(r2);
      float inv = 1.0f / r;
      float ux = px * inv, uy = py * inv, uz = pz * inv;
      const float c3 = 1.73205080756888f;
      const float c5 = 2.23606797749979f;
      const float c15 = 3.87298334620742f;
      Y[0] = 1.0f;
      Y[1] = c3 * ux; Y[2] = c3 * uy; Y[3] = c3 * uz;
      Y[4] = c15 * ux * uy; Y[5] = c15 * uy * uz;
      Y[6] = 0.5f * c5 * (3.0f * uz * uz - 1.0f);
      Y[7] = c15 * ux * uz;
      Y[8] = 0.5f * c15 * (ux * ux - uy * uy);
      float u = fminf(r * 0.2f, 1.0f);
      float u2 = u * u, u4 = u2 * u2, u6 = u4 * u2, u7 = u6 * u, u8 = u4 * u4;
      float fc = 1.0f - 28.0f * u6 + 48.0f * u7 - 21.0f * u8;
      float pref = 0.632455532033676f * inv * fc;
      float w = 0.628318530717958648f * r;
      #pragma unroll
      for (int nb = 1; nb <= 8; nb++) ef[nb - 1] = pref * sinf(w * (float)nb);
      s.recv[tid] = rv;
      s.zs[tid] = ai[sd];
    } else {
      #pragma unroll
      for (int q = 0; q < 9; q++) Y[q] = 0.f;
      #pragma unroll
      for (int q = 0; q < 8; q++) ef[q] = 0.f;
      s.recv[tid] = -1;
      s.zs[tid] = 0;
    }
  }
  __syncthreads();

  gemm128<8,  true >(s.EF, 9,  s.w1, 64, 0, s.Fa, tid); __syncthreads();
  gemm128<64, true >(s.Fa, 68, s.w2, 64, 0, s.Fb, tid); __syncthreads();
  gemm128<64, true >(s.Fb, 68, s.w3, 64, 0, s.Fa, tid); __syncthreads();

  // layer 4 in 3 column-chunks; output stays in registers, scatter directly.
  // No further __syncthreads needed: Fa/Yb/recv/zs are read-only from here on.
  int rg = tid >> 4, cg = tid & 15;
  #pragma unroll
  for (int l = 0; l < 3; l++) {
    float acc[8][4];
    gemm128_reg<64>(s.Fa, 68, s.w4, 192, l * 64, acc, tid);
    int lm0 = (l == 0) ? 0 : ((l == 1) ? 1 : 4);
    int cnt = (l == 0) ? 1 : ((l == 1) ? 3 : 5);
    #pragma unroll
    for (int i = 0; i < 8; i++) {
      int e = rg + 16 * i;
      int rv = s.recv[e];
      if (rv < 0) continue;
      int zz = s.zs[e];
      float4 h4 = *reinterpret_cast<const float4*>(s.htab + zz * 64 + cg * 4);
      float v0 = acc[i][0] * h4.x;
      float v1 = acc[i][1] * h4.y;
      float v2 = acc[i][2] * h4.z;
      float v3 = acc[i][3] * h4.w;
      float* mp = g_msg + rv * 576 + cg * 4;
      const float* Ye = s.Yb + e * 9 + lm0;
      for (int q = 0; q < cnt; q++) {
        float yv = Ye[q];
        float* mq = mp + (lm0 + q) * 64;
        red2(mq,     v0 * yv, v1 * yv);
        red2(mq + 2, v2 * yv, v3 * yv);
      }
    }
  }
}

// ---------------- per-(node,channel) tensor contraction ----------------
// launch_bounds(256,4) caps regs at 64 -> 32 warps/SM (occ 50% vs R2's 37%).
__global__ void __launch_bounds__(256, 4)
contract_kernel(const int* __restrict__ ai,
                const float* __restrict__ U3, const float* __restrict__ U2,
                const float* __restrict__ U1,
                const float* __restrict__ Wc3, const float* __restrict__ Wc2,
                const float* __restrict__ Wc1, int N) {
  __shared__ float4 sU3[729];  // [i][j][k] x p
  __shared__ float4 sU2[81];
  __shared__ float4 sU1[9];
  __shared__ float sW3[ZDIM * 4 * CDIM];
  __shared__ float sW2[ZDIM * 4 * CDIM];
  __shared__ float sW1[ZDIM * 4 * CDIM];
  int tid = threadIdx.x;
  for (int i = tid; i < 729; i += 256) sU3[i] = ((const float4*)U3)[i];
  for (int i = tid; i < 81;  i += 256) sU2[i] = ((const float4*)U2)[i];
  if (tid < 9) sU1[tid] = ((const float4*)U1)[tid];
  for (int i = tid; i < ZDIM * 64; i += 256) {
    ((float4*)sW3)[i] = ((const float4*)Wc3)[i];
    ((float4*)sW2)[i] = ((const float4*)Wc2)[i];
    ((float4*)sW1)[i] = ((const float4*)Wc1)[i];
  }
  __syncthreads();

  int idx = blockIdx.x * 256 + tid;
  if (idx >= N * 64) return;
  int n = idx >> 6, c = idx & 63;
  int z = ai[n];

  float x[9];
  const float* mrow = g_msg + n * 576 + c;
  #pragma unroll
  for (int i = 0; i < 9; i++) x[i] = mrow[i * 64] * (1.0f / 16.0f);  // /AVG

  float w3p0 = sW3[z * 256 + 0 * 64 + c], w3p1 = sW3[z * 256 + 1 * 64 + c];
  float w3p2 = sW3[z * 256 + 2 * 64 + c], w3p3 = sW3[z * 256 + 3 * 64 + c];
  float w2p0 = sW2[z * 256 + 0 * 64 + c], w2p1 = sW2[z * 256 + 1 * 64 + c];
  float w2p2 = sW2[z * 256 + 2 * 64 + c], w2p3 = sW2[z * 256 + 3 * 64 + c];
  float w1p0 = sW1[z * 256 + 0 * 64 + c], w1p1 = sW1[z * 256 + 1 * 64 + c];
  float w1p2 = sW1[z * 256 + 2 * 64 + c], w1p3 = sW1[z * 256 + 3 * 64 + c];

  float res = 0.f;
  for (int j = 0; j < 9; j++) {
    float vj = 0.f;
    for (int k = 0; k < 9; k++) {
      // s_p = sum_i U3[i,j,k,p] * x_i  -- 4 running accumulators (low reg count)
      float s0 = 0.f, s1 = 0.f, s2 = 0.f, s3 = 0.f;
      #pragma unroll
      for (int i = 0; i < 9; i++) {
        float4 u3 = sU3[i * 81 + j * 9 + k];
        float xi = x[i];
        s0 = fmaf(u3.x, xi, s0);
        s1 = fmaf(u3.y, xi, s1);
        s2 = fmaf(u3.z, xi, s2);
        s3 = fmaf(u3.w, xi, s3);
      }
      float4 u2 = sU2[j * 9 + k];
      float t = u2.x * w2p0 + u2.y * w2p1 + u2.z * w2p2 + u2.w * w2p3;
      t = fmaf(s0, w3p0, t);
      t = fmaf(s1, w3p1, t);
      t = fmaf(s2, w3p2, t);
      t = fmaf(s3, w3p3, t);
      vj = fmaf(t, x[k], vj);
    }
    float4 u1 = sU1[j];
    vj += u1.x * w1p0 + u1.y * w1p1 + u1.z * w1p2 + u1.w * w1p3;
    res = fmaf(vj, x[j], res);
  }
  g_xout[idx] = res;
}

// ---------------- final output GEMM: out = xout @ W_out / 8 ----------------
__global__ void __launch_bounds__(256)
out_kernel(const float* __restrict__ W_out, float* __restrict__ out, int N) {
  __shared__ float sW[64 * 64];
  __shared__ float sX[64 * 68];
  int tid = threadIdx.x;
  int n0 = blockIdx.x * 64;
  for (int i = tid; i < 1024; i += 256) ((float4*)sW)[i] = ((const float4*)W_out)[i];
  for (int i = tid; i < 64 * 16; i += 256) {
    int r = i >> 4, c4 = i & 15;
    float4 v = make_float4(0.f, 0.f, 0.f, 0.f);
    if (n0 + r < N) v = *reinterpret_cast<const float4*>(g_xout + (n0 + r) * 64 + c4 * 4);
    *reinterpret_cast<float4*>(sX + r * 68 + c4 * 4) = v;
  }
  __syncthreads();
  int rg = tid >> 4, cg = tid & 15;
  float acc[4][4];
  #pragma unroll
  for (int i = 0; i < 4; i++) { acc[i][0] = 0.f; acc[i][1] = 0.f; acc[i][2] = 0.f; acc[i][3] = 0.f; }
  #pragma unroll 4
  for (int k = 0; k < 64; k++) {
    float4 b = *reinterpret_cast<const float4*>(sW + k * 64 + cg * 4);
    #pragma unroll
    for (int i = 0; i < 4; i++) {
      float a = sX[(rg + 16 * i) * 68 + k];
      acc[i][0] = fmaf(a, b.x, acc[i][0]);
      acc[i][1] = fmaf(a, b.y, acc[i][1]);
      acc[i][2] = fmaf(a, b.z, acc[i][2]);
      acc[i][3] = fmaf(a, b.w, acc[i][3]);
    }
  }
  #pragma unroll
  for (int i = 0; i < 4; i++) {
    int n = n0 + rg + 16 * i;
    if (n < N) {
      *reinterpret_cast<float4*>(out + n * 64 + cg * 4) =
          make_float4(acc[i][0] * 0.125f, acc[i][1] * 0.125f,
                      acc[i][2] * 0.125f, acc[i][3] * 0.125f);
    }
  }
}

// ---------------- launch ----------------
extern "C" void kernel_launch(void* const* d_in, const int* in_sizes, int n_in,
                              void* d_out, int out_size) {
  const float* positions = (const float*)d_in[0];
  const int*   ai        = (const int*)d_in[1];
  const int*   ei        = (const int*)d_in[2];
  const float* W_embed   = (const float*)d_in[3];
  const float* W_up      = (const float*)d_in[4];
  const float* w1        = (const float*)d_in[5];
  const float* w2        = (const float*)d_in[6];
  const float* w3        = (const float*)d_in[7];
  const float* w4        = (const float*)d_in[8];
  const float* U3        = (const float*)d_in[9];
  const float* U2        = (const float*)d_in[10];
  const float* U1        = (const float*)d_in[11];
  const float* Wc3       = (const float*)d_in[12];
  const float* Wc2       = (const float*)d_in[13];
  const float* Wc1       = (const float*)d_in[14];
  const float* W_out     = (const float*)d_in[15];
  float* out = (float*)d_out;

  int N = in_sizes[0] / 3;
  int E = in_sizes[2] / 2;

  cudaFuncSetAttribute(edge_kernel, cudaFuncAttributeMaxDynamicSharedMemorySize,
                       (int)sizeof(ESmem));

  int msg4 = (N * 576) / 4;
  zero_msg_kernel<<<(msg4 + 255) / 256, 256>>>(msg4);
  htable_kernel<<<1, 640>>>(W_embed, W_up);
  int ntiles = (E + 127) / 128;
  edge_kernel<<<ntiles, 256, sizeof(ESmem)>>>(positions, ai, ei, w1, w2, w3, w4, E);
  int nc = N * 64;
  contract_kernel<<<(nc + 255) / 256, 256>>>(ai, U3, U2, U1, Wc3, Wc2, Wc1, N);
  out_kernel<<<(N + 63) / 64, 256>>>(W_out, out, N);

  (void)n_in; (void)out_size;
}

// round 5
// speedup vs baseline: 2.0639x; 1.4964x over previous
#include <cuda_runtime.h>
#include <math.h>

#define NMAX 20000
#define CDIM 64
#define NLMD 9
#define NBES 8
#define ZDIM 10

// ---------------- scratch (device globals; no allocation) ----------------
__device__ float g_msg[NMAX * NLMD * CDIM];   // [N][lm][c]  46.08 MB
__device__ float g_htable[ZDIM * CDIM];
__device__ float g_xout[NMAX * CDIM];
__device__ float g_U3s[NLMD * 45 * 4];        // symmetrized U3: [i][pair][p]
__device__ float g_U2s[45 * 4];               // symmetrized U2: [pair][p]

// ---------------- zero the message buffer ----------------
__global__ void zero_msg_kernel(int n4) {
  int i = blockIdx.x * blockDim.x + threadIdx.x;
  float4* p = reinterpret_cast<float4*>(g_msg);
  if (i < n4) p[i] = make_float4(0.f, 0.f, 0.f, 0.f);
}

// ---------------- species embedding table ----------------
__global__ void htable_kernel(const float* __restrict__ W_embed,
                              const float* __restrict__ W_up) {
  int t = threadIdx.x;
  if (t < ZDIM * CDIM) {
    int z = t >> 6, c = t & 63;
    float acc = 0.f;
    #pragma unroll 8
    for (int k = 0; k < CDIM; k++)
      acc = fmaf(W_embed[z * CDIM + k], W_up[k * CDIM + c], acc);
    g_htable[t] = acc * (1.0f / (3.16227766016838f * 8.0f));  // /(sqrt(10)*sqrt(64))
  }
}

// ---------------- symmetrize U3/U2 over (j,k) ----------------
__global__ void symU_kernel(const float* __restrict__ U3,
                            const float* __restrict__ U2) {
  int t = blockIdx.x * blockDim.x + threadIdx.x;
  if (t >= 9 * 45) return;
  int i = t / 45, pr = t % 45;
  // decode pair index -> (j,k), j <= k
  int j = 0, k = 0, acc = 0;
  for (int jj = 0; jj < 9; jj++) {
    int cnt = 9 - jj;
    if (pr < acc + cnt) { j = jj; k = jj + (pr - acc); break; }
    acc += cnt;
  }
  #pragma unroll
  for (int p = 0; p < 4; p++) {
    float v = U3[((i * 9 + j) * 9 + k) * 4 + p];
    if (j != k) v += U3[((i * 9 + k) * 9 + j) * 4 + p];
    g_U3s[(i * 45 + pr) * 4 + p] = v;
  }
  if (i == 0) {
    #pragma unroll
    for (int p = 0; p < 4; p++) {
      float v = U2[(j * 9 + k) * 4 + p];
      if (j != k) v += U2[(k * 9 + j) * 4 + p];
      g_U2s[pr * 4 + p] = v;
    }
  }
}

// ---------------- fused edge kernel (2 blocks/SM, chunked weights) --------
struct ESmem2 {
  float wbuf[2][4096];     // double-buffered 64x64 weight chunk (2 x 16 KB)
  float w1s[NBES * CDIM];  // 2 KB
  float htab[ZDIM * CDIM]; // 2.5 KB
  float Fa[128 * 68];      // activation ping (34.8 KB)
  float Fb[128 * 68];      // activation pong; EF (stride 9) overlaid at start
  float Yb[128 * 9];
  int   recv[128];
  int   zs[128];
};

// C[128x64] = act(A[128xK] @ B[K x 64]), C stride 68.
template <int K, bool ACT>
__device__ __forceinline__ void gemm128(const float* __restrict__ A, int As,
                                        const float* __restrict__ B,
                                        float* __restrict__ Cm, int tid) {
  int rg = tid >> 4, cg = tid & 15;
  float acc[8][4];
  #pragma unroll
  for (int i = 0; i < 8; i++) { acc[i][0] = 0.f; acc[i][1] = 0.f; acc[i][2] = 0.f; acc[i][3] = 0.f; }
  #pragma unroll 4
  for (int k = 0; k < K; k++) {
    float4 b = *reinterpret_cast<const float4*>(B + k * 64 + cg * 4);
    #pragma unroll
    for (int i = 0; i < 8; i++) {
      float a = A[(rg + 16 * i) * As + k];
      acc[i][0] = fmaf(a, b.x, acc[i][0]);
      acc[i][1] = fmaf(a, b.y, acc[i][1]);
      acc[i][2] = fmaf(a, b.z, acc[i][2]);
      acc[i][3] = fmaf(a, b.w, acc[i][3]);
    }
  }
  #pragma unroll
  for (int i = 0; i < 8; i++) {
    float vv0 = acc[i][0], vv1 = acc[i][1], vv2 = acc[i][2], vv3 = acc[i][3];
    if (ACT) {
      vv0 = vv0 / (1.0f + __expf(-vv0));
      vv1 = vv1 / (1.0f + __expf(-vv1));
      vv2 = vv2 / (1.0f + __expf(-vv2));
      vv3 = vv3 / (1.0f + __expf(-vv3));
    }
    *reinterpret_cast<float4*>(Cm + (rg + 16 * i) * 68 + cg * 4) =
        make_float4(vv0, vv1, vv2, vv3);
  }
}

// load one 64x64 chunk of w4 (cols l*64..l*64+63) into registers
__device__ __forceinline__ void load_w4chunk(float4 pre[4], const float* __restrict__ w4,
                                             int l, int tid) {
  #pragma unroll
  for (int q = 0; q < 4; q++) {
    int f = tid + q * 256, k = f >> 4, c4 = f & 15;
    pre[q] = *reinterpret_cast<const float4*>(w4 + k * 192 + l * 64 + c4 * 4);
  }
}
__device__ __forceinline__ void store_chunk(float* __restrict__ sm, float4 pre[4], int tid) {
  #pragma unroll
  for (int q = 0; q < 4; q++)
    reinterpret_cast<float4*>(sm)[tid + q * 256] = pre[q];
}

extern __shared__ float esmem_raw[];

// R2-proven scatter: warp-per-edge, lanes cover channels, plain atomicAdd
__device__ __forceinline__ void scatter_l(const ESmem2& s, int l, int tid) {
  int wid = tid >> 5, lane = tid & 31;
  int lm0 = (l == 0) ? 0 : ((l == 1) ? 1 : 4);
  int cnt = (l == 0) ? 1 : ((l == 1) ? 3 : 5);
  for (int e = wid; e < 128; e += 8) {
    int rv = s.recv[e];
    if (rv < 0) continue;
    int zz = s.zs[e];
    #pragma unroll
    for (int half = 0; half < 2; half++) {
      int c = lane + 32 * half;
      float val = s.htab[zz * 64 + c] * s.Fb[e * 68 + c];
      float* mp = g_msg + rv * 576 + c;
      const float* Ye = s.Yb + e * 9 + lm0;
      for (int q = 0; q < cnt; q++)
        atomicAdd(mp + (lm0 + q) * 64, val * Ye[q]);
    }
  }
}

__global__ void __launch_bounds__(256, 2)
edge_kernel(const float* __restrict__ pos, const int* __restrict__ ai,
            const int* __restrict__ ei,
            const float* __restrict__ w1, const float* __restrict__ w2,
            const float* __restrict__ w3, const float* __restrict__ w4, int E) {
  ESmem2& s = *reinterpret_cast<ESmem2*>(esmem_raw);
  int tid = threadIdx.x;

  // phase 0: stage w1, htab, w2->wbuf0, w3->wbuf1
  {
    float4* d; const float4* g;
    d = (float4*)s.w1s;  g = (const float4*)w1;       for (int i = tid; i < NBES * CDIM / 4; i += 256) d[i] = g[i];
    d = (float4*)s.htab; g = (const float4*)g_htable; for (int i = tid; i < ZDIM * CDIM / 4; i += 256) d[i] = g[i];
    d = (float4*)s.wbuf[0]; g = (const float4*)w2;    for (int i = tid; i < 1024; i += 256) d[i] = g[i];
    d = (float4*)s.wbuf[1]; g = (const float4*)w3;    for (int i = tid; i < 1024; i += 256) d[i] = g[i];
  }

  // geometry -> EF (overlaid at start of Fb, stride 9), Yb, recv, zs
  if (tid < 128) {
    int eg = blockIdx.x * 128 + tid;
    float* Y  = s.Yb + tid * 9;
    float* ef = s.Fb + tid * 9;  // EF overlay
    if (eg < E) {
      int sd = ei[eg];
      int rv = ei[E + eg];
      float px = pos[3 * rv + 0] - pos[3 * sd + 0];
      float py = pos[3 * rv + 1] - pos[3 * sd + 1];
      float pz = pos[3 * rv + 2] - pos[3 * sd + 2];
      float r2 = px * px + py * py + pz * pz + 1e-12f;
      float r = sqrtf(r2);
      float inv = 1.0f / r;
      float ux = px * inv, uy = py * inv, uz = pz * inv;
      const float c3 = 1.73205080756888f;
      const float c5 = 2.23606797749979f;
      const float c15 = 3.87298334620742f;
      Y[0] = 1.0f;
      Y[1] = c3 * ux; Y[2] = c3 * uy; Y[3] = c3 * uz;
      Y[4] = c15 * ux * uy; Y[5] = c15 * uy * uz;
      Y[6] = 0.5f * c5 * (3.0f * uz * uz - 1.0f);
      Y[7] = c15 * ux * uz;
      Y[8] = 0.5f * c15 * (ux * ux - uy * uy);
      float u = fminf(r * 0.2f, 1.0f);
      float u2 = u * u, u4 = u2 * u2, u6 = u4 * u2, u7 = u6 * u, u8 = u4 * u4;
      float fc = 1.0f - 28.0f * u6 + 48.0f * u7 - 21.0f * u8;
      float pref = 0.632455532033676f * inv * fc;
      float w = 0.628318530717958648f * r;
      #pragma unroll
      for (int nb = 1; nb <= 8; nb++) ef[nb - 1] = pref * sinf(w * (float)nb);
      s.recv[tid] = rv;
      s.zs[tid] = ai[sd];
    } else {
      #pragma unroll
      for (int q = 0; q < 9; q++) Y[q] = 0.f;
      #pragma unroll
      for (int q = 0; q < 8; q++) ef[q] = 0.f;
      s.recv[tid] = -1;
      s.zs[tid] = 0;
    }
  }
  __syncthreads();

  // L1: EF(@Fb overlay) @ w1 -> Fa
  gemm128<8, true>(s.Fb, 9, s.w1s, s.Fa, tid);
  __syncthreads();

  // L2: Fa @ w2(wbuf0) -> Fb   (prefetch w4 chunk 0 during)
  float4 preA[4], preB[4];
  load_w4chunk(preA, w4, 0, tid);
  gemm128<64, true>(s.Fa, 68, s.wbuf[0], s.Fb, tid);
  __syncthreads();                       // Fb ready, wbuf0 free

  store_chunk(s.wbuf[0], preA, tid);     // wbuf0 <- w4 chunk 0
  load_w4chunk(preB, w4, 1, tid);
  // L3: Fb @ w3(wbuf1) -> Fa
  gemm128<64, true>(s.Fb, 68, s.wbuf[1], s.Fa, tid);
  __syncthreads();                       // Fa ready, wbuf1 free, wbuf0 visible

  store_chunk(s.wbuf[1], preB, tid);     // wbuf1 <- w4 chunk 1
  load_w4chunk(preA, w4, 2, tid);
  // L4 chunk 0: Fa @ w4a(wbuf0) -> Fb, scatter l=0
  gemm128<64, false>(s.Fa, 68, s.wbuf[0], s.Fb, tid);
  __syncthreads();                       // Fb(l0) ready, wbuf1 visible
  scatter_l(s, 0, tid);
  __syncthreads();                       // scatter done before Fb overwritten; wbuf0 free

  store_chunk(s.wbuf[0], preA, tid);     // wbuf0 <- w4 chunk 2
  // L4 chunk 1
  gemm128<64, false>(s.Fa, 68, s.wbuf[1], s.Fb, tid);
  __syncthreads();                       // Fb(l1) ready, wbuf0 visible
  scatter_l(s, 1, tid);
  __syncthreads();
  // L4 chunk 2
  gemm128<64, false>(s.Fa, 68, s.wbuf[0], s.Fb, tid);
  __syncthreads();
  scatter_l(s, 2, tid);
}

// ---------------- per-(node,channel) tensor contraction (symmetrized) -----
__global__ void __launch_bounds__(256, 4)
contract_kernel(const int* __restrict__ ai, const float* __restrict__ U1,
                const float* __restrict__ Wc3, const float* __restrict__ Wc2,
                const float* __restrict__ Wc1, int N) {
  __shared__ float4 sU3s[9 * 45];  // [i][pair] x p
  __shared__ float4 sU2s[45];
  __shared__ float4 sU1[9];
  __shared__ float sW3[ZDIM * 4 * CDIM];
  __shared__ float sW2[ZDIM * 4 * CDIM];
  __shared__ float sW1[ZDIM * 4 * CDIM];
  int tid = threadIdx.x;
  for (int i = tid; i < 9 * 45; i += 256) sU3s[i] = ((const float4*)g_U3s)[i];
  if (tid < 45) sU2s[tid] = ((const float4*)g_U2s)[tid];
  if (tid >= 64 && tid < 73) sU1[tid - 64] = ((const float4*)U1)[tid - 64];
  for (int i = tid; i < ZDIM * 64; i += 256) {
    ((float4*)sW3)[i] = ((const float4*)Wc3)[i];
    ((float4*)sW2)[i] = ((const float4*)Wc2)[i];
    ((float4*)sW1)[i] = ((const float4*)Wc1)[i];
  }
  __syncthreads();

  int idx = blockIdx.x * 256 + tid;
  if (idx >= N * 64) return;
  int n = idx >> 6, c = idx & 63;
  int z = ai[n];

  float x[9];
  const float* mrow = g_msg + n * 576 + c;
  #pragma unroll
  for (int i = 0; i < 9; i++) x[i] = mrow[i * 64] * (1.0f / 16.0f);  // /AVG

  float w3p0 = sW3[z * 256 + 0 * 64 + c], w3p1 = sW3[z * 256 + 1 * 64 + c];
  float w3p2 = sW3[z * 256 + 2 * 64 + c], w3p3 = sW3[z * 256 + 3 * 64 + c];
  float w2p0 = sW2[z * 256 + 0 * 64 + c], w2p1 = sW2[z * 256 + 1 * 64 + c];
  float w2p2 = sW2[z * 256 + 2 * 64 + c], w2p3 = sW2[z * 256 + 3 * 64 + c];
  float w1p0 = sW1[z * 256 + 0 * 64 + c], w1p1 = sW1[z * 256 + 1 * 64 + c];
  float w1p2 = sW1[z * 256 + 2 * 64 + c], w1p3 = sW1[z * 256 + 3 * 64 + c];

  float res = 0.f;
  int pr = 0;
  for (int j = 0; j < 9; j++) {
    float xj = x[j];
    for (int k = j; k < 9; k++, pr++) {
      float X2 = xj * x[k];
      float s0 = 0.f, s1 = 0.f, s2 = 0.f, s3 = 0.f;
      #pragma unroll
      for (int i = 0; i < 9; i++) {
        float4 u3 = sU3s[i * 45 + pr];
        float xi = x[i];
        s0 = fmaf(u3.x, xi, s0);
        s1 = fmaf(u3.y, xi, s1);
        s2 = fmaf(u3.z, xi, s2);
        s3 = fmaf(u3.w, xi, s3);
      }
      float4 u2 = sU2s[pr];
      float t = u2.x * w2p0 + u2.y * w2p1 + u2.z * w2p2 + u2.w * w2p3;
      t = fmaf(s0, w3p0, t);
      t = fmaf(s1, w3p1, t);
      t = fmaf(s2, w3p2, t);
      t = fmaf(s3, w3p3, t);
      res = fmaf(t, X2, res);
    }
  }
  // U1 linear term
  #pragma unroll
  for (int j = 0; j < 9; j++) {
    float4 u1 = sU1[j];
    float v = u1.x * w1p0 + u1.y * w1p1 + u1.z * w1p2 + u1.w * w1p3;
    res = fmaf(v, x[j], res);
  }
  g_xout[idx] = res;
}

// ---------------- final output GEMM: out = xout @ W_out / 8 ----------------
__global__ void __launch_bounds__(256)
out_kernel(const float* __restrict__ W_out, float* __restrict__ out, int N) {
  __shared__ float sW[64 * 64];
  __shared__ float sX[64 * 68];
  int tid = threadIdx.x;
  int n0 = blockIdx.x * 64;
  for (int i = tid; i < 1024; i += 256) ((float4*)sW)[i] = ((const float4*)W_out)[i];
  for (int i = tid; i < 64 * 16; i += 256) {
    int r = i >> 4, c4 = i & 15;
    float4 v = make_float4(0.f, 0.f, 0.f, 0.f);
    if (n0 + r < N) v = *reinterpret_cast<const float4*>(g_xout + (n0 + r) * 64 + c4 * 4);
    *reinterpret_cast<float4*>(sX + r * 68 + c4 * 4) = v;
  }
  __syncthreads();
  int rg = tid >> 4, cg = tid & 15;
  float acc[4][4];
  #pragma unroll
  for (int i = 0; i < 4; i++) { acc[i][0] = 0.f; acc[i][1] = 0.f; acc[i][2] = 0.f; acc[i][3] = 0.f; }
  #pragma unroll 4
  for (int k = 0; k < 64; k++) {
    float4 b = *reinterpret_cast<const float4*>(sW + k * 64 + cg * 4);
    #pragma unroll
    for (int i = 0; i < 4; i++) {
      float a = sX[(rg + 16 * i) * 68 + k];
      acc[i][0] = fmaf(a, b.x, acc[i][0]);
      acc[i][1] = fmaf(a, b.y, acc[i][1]);
      acc[i][2] = fmaf(a, b.z, acc[i][2]);
      acc[i][3] = fmaf(a, b.w, acc[i][3]);
    }
  }
  #pragma unroll
  for (int i = 0; i < 4; i++) {
    int n = n0 + rg + 16 * i;
    if (n < N) {
      *reinterpret_cast<float4*>(out + n * 64 + cg * 4) =
          make_float4(acc[i][0] * 0.125f, acc[i][1] * 0.125f,
                      acc[i][2] * 0.125f, acc[i][3] * 0.125f);
    }
  }
}

// ---------------- launch ----------------
extern "C" void kernel_launch(void* const* d_in, const int* in_sizes, int n_in,
                              void* d_out, int out_size) {
  const float* positions = (const float*)d_in[0];
  const int*   ai        = (const int*)d_in[1];
  const int*   ei        = (const int*)d_in[2];
  const float* W_embed   = (const float*)d_in[3];
  const float* W_up      = (const float*)d_in[4];
  const float* w1        = (const float*)d_in[5];
  const float* w2        = (const float*)d_in[6];
  const float* w3        = (const float*)d_in[7];
  const float* w4        = (const float*)d_in[8];
  const float* U3        = (const float*)d_in[9];
  const float* U2        = (const float*)d_in[10];
  const float* U1        = (const float*)d_in[11];
  const float* Wc3       = (const float*)d_in[12];
  const float* Wc2       = (const float*)d_in[13];
  const float* Wc1       = (const float*)d_in[14];
  const float* W_out     = (const float*)d_in[15];
  float* out = (float*)d_out;

  int N = in_sizes[0] / 3;
  int E = in_sizes[2] / 2;

  cudaFuncSetAttribute(edge_kernel, cudaFuncAttributeMaxDynamicSharedMemorySize,
                       (int)sizeof(ESmem2));

  int msg4 = (N * 576) / 4;
  zero_msg_kernel<<<(msg4 + 255) / 256, 256>>>(msg4);
  htable_kernel<<<1, 640>>>(W_embed, W_up);
  symU_kernel<<<2, 256>>>(U3, U2);
  int ntiles = (E + 127) / 128;
  edge_kernel<<<ntiles, 256, sizeof(ESmem2)>>>(positions, ai, ei, w1, w2, w3, w4, E);
  int nc = N * 64;
  contract_kernel<<<(nc + 255) / 256, 256>>>(ai, U1, Wc3, Wc2, Wc1, N);
  out_kernel<<<(N + 63) / 64, 256>>>(W_out, out, N);

  (void)n_in; (void)out_size;
}

// round 8
// speedup vs baseline: 2.1245x; 1.0293x over previous
#include <cuda_runtime.h>
#include <math.h>

#define NMAX 20000
#define CDIM 64
#define NLMD 9
#define NBES 8
#define ZDIM 10

// ---------------- scratch (device globals; no allocation) ----------------
__device__ float g_msg[NMAX * NLMD * CDIM];   // [N][lm][c]  46.08 MB
__device__ float g_htable[ZDIM * CDIM];
__device__ float g_xout[NMAX * CDIM];
__device__ float g_U3s[NLMD * 45 * 4];        // symmetrized U3: [i][pair][p]
__device__ float g_U2s[45 * 4];               // symmetrized U2: [pair][p]

// ---------------- zero the message buffer ----------------
__global__ void zero_msg_kernel(int n4) {
  int i = blockIdx.x * blockDim.x + threadIdx.x;
  float4* p = reinterpret_cast<float4*>(g_msg);
  if (i < n4) p[i] = make_float4(0.f, 0.f, 0.f, 0.f);
}

// ---------------- species embedding table ----------------
__global__ void htable_kernel(const float* __restrict__ W_embed,
                              const float* __restrict__ W_up) {
  int t = threadIdx.x;
  if (t < ZDIM * CDIM) {
    int z = t >> 6, c = t & 63;
    float acc = 0.f;
    #pragma unroll 8
    for (int k = 0; k < CDIM; k++)
      acc = fmaf(W_embed[z * CDIM + k], W_up[k * CDIM + c], acc);
    g_htable[t] = acc * (1.0f / (3.16227766016838f * 8.0f));  // /(sqrt(10)*sqrt(64))
  }
}

// ---------------- symmetrize U3/U2 over (j,k) ----------------
__global__ void symU_kernel(const float* __restrict__ U3,
                            const float* __restrict__ U2) {
  int t = blockIdx.x * blockDim.x + threadIdx.x;
  if (t >= 9 * 45) return;
  int i = t / 45, pr = t % 45;
  int j = 0, k = 0, acc = 0;
  for (int jj = 0; jj < 9; jj++) {
    int cnt = 9 - jj;
    if (pr < acc + cnt) { j = jj; k = jj + (pr - acc); break; }
    acc += cnt;
  }
  #pragma unroll
  for (int p = 0; p < 4; p++) {
    float v = U3[((i * 9 + j) * 9 + k) * 4 + p];
    if (j != k) v += U3[((i * 9 + k) * 9 + j) * 4 + p];
    g_U3s[(i * 45 + pr) * 4 + p] = v;
  }
  if (i == 0) {
    #pragma unroll
    for (int p = 0; p < 4; p++) {
      float v = U2[(j * 9 + k) * 4 + p];
      if (j != k) v += U2[(k * 9 + j) * 4 + p];
      g_U2s[pr * 4 + p] = v;
    }
  }
}

// ---------------- fused edge kernel (2 blocks/SM, chunked weights) --------
struct ESmem2 {
  float wbuf[2][4096];     // double-buffered 64x64 weight chunk
  float w1s[NBES * CDIM];
  float htab[ZDIM * CDIM];
  float Fa[128 * 68];      // activation ping
  float Fb[128 * 68];      // activation pong; EF (stride 9) overlaid at start
  float Yb[128 * 9];
  int   recv[128];
  int   zs[128];
};

// Scalar-A GEMM (used for layer 1 only; A stride not 16B-aligned).
template <int K, bool ACT>
__device__ __forceinline__ void gemm128(const float* __restrict__ A, int As,
                                        const float* __restrict__ B,
                                        float* __restrict__ Cm, int tid) {
  int rg = tid >> 4, cg = tid & 15;
  float acc[8][4];
  #pragma unroll
  for (int i = 0; i < 8; i++) { acc[i][0] = 0.f; acc[i][1] = 0.f; acc[i][2] = 0.f; acc[i][3] = 0.f; }
  #pragma unroll 4
  for (int k = 0; k < K; k++) {
    float4 b = *reinterpret_cast<const float4*>(B + k * 64 + cg * 4);
    #pragma unroll
    for (int i = 0; i < 8; i++) {
      float a = A[(rg + 16 * i) * As + k];
      acc[i][0] = fmaf(a, b.x, acc[i][0]);
      acc[i][1] = fmaf(a, b.y, acc[i][1]);
      acc[i][2] = fmaf(a, b.z, acc[i][2]);
      acc[i][3] = fmaf(a, b.w, acc[i][3]);
    }
  }
  #pragma unroll
  for (int i = 0; i < 8; i++) {
    float vv0 = acc[i][0], vv1 = acc[i][1], vv2 = acc[i][2], vv3 = acc[i][3];
    if (ACT) {
      vv0 = vv0 / (1.0f + __expf(-vv0));
      vv1 = vv1 / (1.0f + __expf(-vv1));
      vv2 = vv2 / (1.0f + __expf(-vv2));
      vv3 = vv3 / (1.0f + __expf(-vv3));
    }
    *reinterpret_cast<float4*>(Cm + (rg + 16 * i) * 68 + cg * 4) =
        make_float4(vv0, vv1, vv2, vv3);
  }
}

// float4-A GEMM, K multiple of 4, A stride 68 (16B-aligned rows).
// Per 4 k-steps: 8 A LDS.128 + 4 B LDS.128 + 128 FFMA (vs 36 LDS + 128 FFMA scalar).
template <int K, bool ACT>
__device__ __forceinline__ void gemm128v(const float* __restrict__ A,
                                         const float* __restrict__ B,
                                         float* __restrict__ Cm, int tid) {
  int rg = tid >> 4, cg = tid & 15;
  float acc[8][4];
  #pragma unroll
  for (int i = 0; i < 8; i++) { acc[i][0] = 0.f; acc[i][1] = 0.f; acc[i][2] = 0.f; acc[i][3] = 0.f; }
  #pragma unroll 2
  for (int k0 = 0; k0 < K; k0 += 4) {
    float4 b0 = *reinterpret_cast<const float4*>(B + (k0 + 0) * 64 + cg * 4);
    float4 b1 = *reinterpret_cast<const float4*>(B + (k0 + 1) * 64 + cg * 4);
    float4 b2 = *reinterpret_cast<const float4*>(B + (k0 + 2) * 64 + cg * 4);
    float4 b3 = *reinterpret_cast<const float4*>(B + (k0 + 3) * 64 + cg * 4);
    #pragma unroll
    for (int i = 0; i < 8; i++) {
      float4 a = *reinterpret_cast<const float4*>(A + (rg + 16 * i) * 68 + k0);
      acc[i][0] = fmaf(a.x, b0.x, acc[i][0]);
      acc[i][1] = fmaf(a.x, b0.y, acc[i][1]);
      acc[i][2] = fmaf(a.x, b0.z, acc[i][2]);
      acc[i][3] = fmaf(a.x, b0.w, acc[i][3]);
      acc[i][0] = fmaf(a.y, b1.x, acc[i][0]);
      acc[i][1] = fmaf(a.y, b1.y, acc[i][1]);
      acc[i][2] = fmaf(a.y, b1.z, acc[i][2]);
      acc[i][3] = fmaf(a.y, b1.w, acc[i][3]);
      acc[i][0] = fmaf(a.z, b2.x, acc[i][0]);
      acc[i][1] = fmaf(a.z, b2.y, acc[i][1]);
      acc[i][2] = fmaf(a.z, b2.z, acc[i][2]);
      acc[i][3] = fmaf(a.z, b2.w, acc[i][3]);
      acc[i][0] = fmaf(a.w, b3.x, acc[i][0]);
      acc[i][1] = fmaf(a.w, b3.y, acc[i][1]);
      acc[i][2] = fmaf(a.w, b3.z, acc[i][2]);
      acc[i][3] = fmaf(a.w, b3.w, acc[i][3]);
    }
  }
  #pragma unroll
  for (int i = 0; i < 8; i++) {
    float vv0 = acc[i][0], vv1 = acc[i][1], vv2 = acc[i][2], vv3 = acc[i][3];
    if (ACT) {
      vv0 = vv0 / (1.0f + __expf(-vv0));
      vv1 = vv1 / (1.0f + __expf(-vv1));
      vv2 = vv2 / (1.0f + __expf(-vv2));
      vv3 = vv3 / (1.0f + __expf(-vv3));
    }
    *reinterpret_cast<float4*>(Cm + (rg + 16 * i) * 68 + cg * 4) =
        make_float4(vv0, vv1, vv2, vv3);
  }
}

// load one 64x64 chunk of w4 (cols l*64..) into registers
__device__ __forceinline__ void load_w4chunk(float4 pre[4], const float* __restrict__ w4,
                                             int l, int tid) {
  #pragma unroll
  for (int q = 0; q < 4; q++) {
    int f = tid + q * 256, k = f >> 4, c4 = f & 15;
    pre[q] = *reinterpret_cast<const float4*>(w4 + k * 192 + l * 64 + c4 * 4);
  }
}
__device__ __forceinline__ void store_chunk(float* __restrict__ sm, float4 pre[4], int tid) {
  #pragma unroll
  for (int q = 0; q < 4; q++)
    reinterpret_cast<float4*>(sm)[tid + q * 256] = pre[q];
}

extern __shared__ float esmem_raw[];

// warp-per-edge scatter, lanes cover channels, plain atomicAdd
__device__ __forceinline__ void scatter_l(const ESmem2& s, int l, int tid) {
  int wid = tid >> 5, lane = tid & 31;
  int lm0 = (l == 0) ? 0 : ((l == 1) ? 1 : 4);
  int cnt = (l == 0) ? 1 : ((l == 1) ? 3 : 5);
  for (int e = wid; e < 128; e += 8) {
    int rv = s.recv[e];
    if (rv < 0) continue;
    int zz = s.zs[e];
    #pragma unroll
    for (int half = 0; half < 2; half++) {
      int c = lane + 32 * half;
      float val = s.htab[zz * 64 + c] * s.Fb[e * 68 + c];
      float* mp = g_msg + rv * 576 + c;
      const float* Ye = s.Yb + e * 9 + lm0;
      for (int q = 0; q < cnt; q++)
        atomicAdd(mp + (lm0 + q) * 64, val * Ye[q]);
    }
  }
}

__global__ void __launch_bounds__(256, 2)
edge_kernel(const float* __restrict__ pos, const int* __restrict__ ai,
            const int* __restrict__ ei,
            const float* __restrict__ w1, const float* __restrict__ w2,
            const float* __restrict__ w3, const float* __restrict__ w4, int E) {
  ESmem2& s = *reinterpret_cast<ESmem2*>(esmem_raw);
  int tid = threadIdx.x;

  // phase 0: stage w1, htab, w2->wbuf0, w3->wbuf1
  {
    float4* d; const float4* g;
    d = (float4*)s.w1s;  g = (const float4*)w1;       for (int i = tid; i < NBES * CDIM / 4; i += 256) d[i] = g[i];
    d = (float4*)s.htab; g = (const float4*)g_htable; for (int i = tid; i < ZDIM * CDIM / 4; i += 256) d[i] = g[i];
    d = (float4*)s.wbuf[0]; g = (const float4*)w2;    for (int i = tid; i < 1024; i += 256) d[i] = g[i];
    d = (float4*)s.wbuf[1]; g = (const float4*)w3;    for (int i = tid; i < 1024; i += 256) d[i] = g[i];
  }

  // geometry -> EF (overlaid at start of Fb, stride 9), Yb, recv, zs
  if (tid < 128) {
    int eg = blockIdx.x * 128 + tid;
    float* Y  = s.Yb + tid * 9;
    float* ef = s.Fb + tid * 9;  // EF overlay
    if (eg < E) {
      int sd = ei[eg];
      int rv = ei[E + eg];
      float px = pos[3 * rv + 0] - pos[3 * sd + 0];
      float py = pos[3 * rv + 1] - pos[3 * sd + 1];
      float pz = pos[3 * rv + 2] - pos[3 * sd + 2];
      float r2 = px * px + py * py + pz * pz + 1e-12f;
      float r = sqrtf(r2);
      float inv = 1.0f / r;
      float ux = px * inv, uy = py * inv, uz = pz * inv;
      const float c3 = 1.73205080756888f;
      const float c5 = 2.23606797749979f;
      const float c15 = 3.87298334620742f;
      Y[0] = 1.0f;
      Y[1] = c3 * ux; Y[2] = c3 * uy; Y[3] = c3 * uz;
      Y[4] = c15 * ux * uy; Y[5] = c15 * uy * uz;
      Y[6] = 0.5f * c5 * (3.0f * uz * uz - 1.0f);
      Y[7] = c15 * ux * uz;
      Y[8] = 0.5f * c15 * (ux * ux - uy * uy);
      float u = fminf(r * 0.2f, 1.0f);
      float u2 = u * u, u4 = u2 * u2, u6 = u4 * u2, u7 = u6 * u, u8 = u4 * u4;
      float fc = 1.0f - 28.0f * u6 + 48.0f * u7 - 21.0f * u8;
      float pref = 0.632455532033676f * inv * fc;
      float w = 0.628318530717958648f * r;
      #pragma unroll
      for (int nb = 1; nb <= 8; nb++) ef[nb - 1] = pref * sinf(w * (float)nb);
      s.recv[tid] = rv;
      s.zs[tid] = ai[sd];
    } else {
      #pragma unroll
      for (int q = 0; q < 9; q++) Y[q] = 0.f;
      #pragma unroll
      for (int q = 0; q < 8; q++) ef[q] = 0.f;
      s.recv[tid] = -1;
      s.zs[tid] = 0;
    }
  }
  __syncthreads();

  // L1: EF(@Fb overlay, stride 9) @ w1 -> Fa  (scalar-A path)
  gemm128<8, true>(s.Fb, 9, s.w1s, s.Fa, tid);
  __syncthreads();

  // L2: Fa @ w2(wbuf0) -> Fb   (prefetch w4 chunk 0 during)
  float4 preA[4], preB[4];
  load_w4chunk(preA, w4, 0, tid);
  gemm128v<64, true>(s.Fa, s.wbuf[0], s.Fb, tid);
  __syncthreads();                       // Fb ready, wbuf0 free

  store_chunk(s.wbuf[0], preA, tid);     // wbuf0 <- w4 chunk 0
  load_w4chunk(preB, w4, 1, tid);
  // L3: Fb @ w3(wbuf1) -> Fa
  gemm128v<64, true>(s.Fb, s.wbuf[1], s.Fa, tid);
  __syncthreads();                       // Fa ready, wbuf1 free, wbuf0 visible

  store_chunk(s.wbuf[1], preB, tid);     // wbuf1 <- w4 chunk 1
  load_w4chunk(preA, w4, 2, tid);
  // L4 chunk 0: Fa @ w4a(wbuf0) -> Fb, scatter l=0
  gemm128v<64, false>(s.Fa, s.wbuf[0], s.Fb, tid);
  __syncthreads();                       // Fb(l0) ready, wbuf1 visible
  scatter_l(s, 0, tid);
  __syncthreads();                       // scatter done before Fb overwritten; wbuf0 free

  store_chunk(s.wbuf[0], preA, tid);     // wbuf0 <- w4 chunk 2
  // L4 chunk 1
  gemm128v<64, false>(s.Fa, s.wbuf[1], s.Fb, tid);
  __syncthreads();                       // Fb(l1) ready, wbuf0 visible
  scatter_l(s, 1, tid);
  __syncthreads();
  // L4 chunk 2
  gemm128v<64, false>(s.Fa, s.wbuf[0], s.Fb, tid);
  __syncthreads();
  scatter_l(s, 2, tid);
}

// ---------------- per-(node,channel) tensor contraction (symmetrized) -----
__global__ void __launch_bounds__(256, 4)
contract_kernel(const int* __restrict__ ai, const float* __restrict__ U1,
                const float* __restrict__ Wc3, const float* __restrict__ Wc2,
                const float* __restrict__ Wc1, int N) {
  __shared__ float4 sU3s[9 * 45];  // [i][pair] x p
  __shared__ float4 sU2s[45];
  __shared__ float4 sU1[9];
  __shared__ float sW3[ZDIM * 4 * CDIM];
  __shared__ float sW2[ZDIM * 4 * CDIM];
  __shared__ float sW1[ZDIM * 4 * CDIM];
  int tid = threadIdx.x;
  for (int i = tid; i < 9 * 45; i += 256) sU3s[i] = ((const float4*)g_U3s)[i];
  if (tid < 45) sU2s[tid] = ((const float4*)g_U2s)[tid];
  if (tid >= 64 && tid < 73) sU1[tid - 64] = ((const float4*)U1)[tid - 64];
  for (int i = tid; i < ZDIM * 64; i += 256) {
    ((float4*)sW3)[i] = ((const float4*)Wc3)[i];
    ((float4*)sW2)[i] = ((const float4*)Wc2)[i];
    ((float4*)sW1)[i] = ((const float4*)Wc1)[i];
  }
  __syncthreads();

  int idx = blockIdx.x * 256 + tid;
  if (idx >= N * 64) return;
  int n = idx >> 6, c = idx & 63;
  int z = ai[n];

  float x[9];
  const float* mrow = g_msg + n * 576 + c;
  #pragma unroll
  for (int i = 0; i < 9; i++) x[i] = mrow[i * 64] * (1.0f / 16.0f);  // /AVG

  float w3p0 = sW3[z * 256 + 0 * 64 + c], w3p1 = sW3[z * 256 + 1 * 64 + c];
  float w3p2 = sW3[z * 256 + 2 * 64 + c], w3p3 = sW3[z * 256 + 3 * 64 + c];
  float w2p0 = sW2[z * 256 + 0 * 64 + c], w2p1 = sW2[z * 256 + 1 * 64 + c];
  float w2p2 = sW2[z * 256 + 2 * 64 + c], w2p3 = sW2[z * 256 + 3 * 64 + c];
  float w1p0 = sW1[z * 256 + 0 * 64 + c], w1p1 = sW1[z * 256 + 1 * 64 + c];
  float w1p2 = sW1[z * 256 + 2 * 64 + c], w1p3 = sW1[z * 256 + 3 * 64 + c];

  float res = 0.f;
  int pr = 0;
  for (int j = 0; j < 9; j++) {
    float xj = x[j];
    for (int k = j; k < 9; k++, pr++) {
      float X2 = xj * x[k];
      float s0 = 0.f, s1 = 0.f, s2 = 0.f, s3 = 0.f;
      #pragma unroll
      for (int i = 0; i < 9; i++) {
        float4 u3 = sU3s[i * 45 + pr];
        float xi = x[i];
        s0 = fmaf(u3.x, xi, s0);
        s1 = fmaf(u3.y, xi, s1);
        s2 = fmaf(u3.z, xi, s2);
        s3 = fmaf(u3.w, xi, s3);
      }
      float4 u2 = sU2s[pr];
      float t = u2.x * w2p0 + u2.y * w2p1 + u2.z * w2p2 + u2.w * w2p3;
      t = fmaf(s0, w3p0, t);
      t = fmaf(s1, w3p1, t);
      t = fmaf(s2, w3p2, t);
      t = fmaf(s3, w3p3, t);
      res = fmaf(t, X2, res);
    }
  }
  #pragma unroll
  for (int j = 0; j < 9; j++) {
    float4 u1 = sU1[j];
    float v = u1.x * w1p0 + u1.y * w1p1 + u1.z * w1p2 + u1.w * w1p3;
    res = fmaf(v, x[j], res);
  }
  g_xout[idx] = res;
}

// ---------------- final output GEMM: out = xout @ W_out / 8 ----------------
__global__ void __launch_bounds__(256)
out_kernel(const float* __restrict__ W_out, float* __restrict__ out, int N) {
  __shared__ float sW[64 * 64];
  __shared__ float sX[64 * 68];
  int tid = threadIdx.x;
  int n0 = blockIdx.x * 64;
  for (int i = tid; i < 1024; i += 256) ((float4*)sW)[i] = ((const float4*)W_out)[i];
  for (int i = tid; i < 64 * 16; i += 256) {
    int r = i >> 4, c4 = i & 15;
    float4 v = make_float4(0.f, 0.f, 0.f, 0.f);
    if (n0 + r < N) v = *reinterpret_cast<const float4*>(g_xout + (n0 + r) * 64 + c4 * 4);
    *reinterpret_cast<float4*>(sX + r * 68 + c4 * 4) = v;
  }
  __syncthreads();
  int rg = tid >> 4, cg = tid & 15;
  float acc[4][4];
  #pragma unroll
  for (int i = 0; i < 4; i++) { acc[i][0] = 0.f; acc[i][1] = 0.f; acc[i][2] = 0.f; acc[i][3] = 0.f; }
  #pragma unroll 4
  for (int k = 0; k < 64; k++) {
    float4 b = *reinterpret_cast<const float4*>(sW + k * 64 + cg * 4);
    #pragma unroll
    for (int i = 0; i < 4; i++) {
      float a = sX[(rg + 16 * i) * 68 + k];
      acc[i][0] = fmaf(a, b.x, acc[i][0]);
      acc[i][1] = fmaf(a, b.y, acc[i][1]);
      acc[i][2] = fmaf(a, b.z, acc[i][2]);
      acc[i][3] = fmaf(a, b.w, acc[i][3]);
    }
  }
  #pragma unroll
  for (int i = 0; i < 4; i++) {
    int n = n0 + rg + 16 * i;
    if (n < N) {
      *reinterpret_cast<float4*>(out + n * 64 + cg * 4) =
          make_float4(acc[i][0] * 0.125f, acc[i][1] * 0.125f,
                      acc[i][2] * 0.125f, acc[i][3] * 0.125f);
    }
  }
}

// ---------------- launch ----------------
extern "C" void kernel_launch(void* const* d_in, const int* in_sizes, int n_in,
                              void* d_out, int out_size) {
  const float* positions = (const float*)d_in[0];
  const int*   ai        = (const int*)d_in[1];
  const int*   ei        = (const int*)d_in[2];
  const float* W_embed   = (const float*)d_in[3];
  const float* W_up      = (const float*)d_in[4];
  const float* w1        = (const float*)d_in[5];
  const float* w2        = (const float*)d_in[6];
  const float* w3        = (const float*)d_in[7];
  const float* w4        = (const float*)d_in[8];
  const float* U3        = (const float*)d_in[9];
  const float* U2        = (const float*)d_in[10];
  const float* U1        = (const float*)d_in[11];
  const float* Wc3       = (const float*)d_in[12];
  const float* Wc2       = (const float*)d_in[13];
  const float* Wc1       = (const float*)d_in[14];
  const float* W_out     = (const float*)d_in[15];
  float* out = (float*)d_out;

  int N = in_sizes[0] / 3;
  int E = in_sizes[2] / 2;

  cudaFuncSetAttribute(edge_kernel, cudaFuncAttributeMaxDynamicSharedMemorySize,
                       (int)sizeof(ESmem2));

  int msg4 = (N * 576) / 4;
  zero_msg_kernel<<<(msg4 + 255) / 256, 256>>>(msg4);
  htable_kernel<<<1, 640>>>(W_embed, W_up);
  symU_kernel<<<2, 256>>>(U3, U2);
  int ntiles = (E + 127) / 128;
  edge_kernel<<<ntiles, 256, sizeof(ESmem2)>>>(positions, ai, ei, w1, w2, w3, w4, E);
  int nc = N * 64;
  contract_kernel<<<(nc + 255) / 256, 256>>>(ai, U1, Wc3, Wc2, Wc1, N);
  out_kernel<<<(N + 63) / 64, 256>>>(W_out, out, N);

  (void)n_in; (void)out_size;
}